// round 1
// baseline (speedup 1.0000x reference)
#include <cuda_runtime.h>

// Problem constants
constexpr int Dd   = 256;       // latent dim
constexpr int HW   = 4096;      // 64*64
constexpr int NPIX = 65536;     // 16*64*64
constexpr int KK   = 1024;      // codebook size
constexpr int NOUT = 16777216;  // 16*256*64*64

// Scratch (static device globals; no allocations allowed)
__device__ float g_t1[NPIX];     // ||z_p||^2  (fp64-accumulated, rounded to f32)
__device__ float g_t2[KK];       // ||e_k||^2
__device__ int   g_idx[NPIX];    // argmin indices
__device__ float g_part[NPIX / 32]; // per-block loss partials (2048)

// ---------------------------------------------------------------------------
// ||e_k||^2
__global__ void t2_kernel(const float* __restrict__ emb) {
    int k = blockIdx.x * blockDim.x + threadIdx.x;
    if (k < KK) {
        const float* row = emb + (size_t)k * Dd;
        double s = 0.0;
        #pragma unroll 8
        for (int d = 0; d < Dd; d++) { double v = (double)row[d]; s += v * v; }
        g_t2[k] = (float)s;
    }
}

// ||z_p||^2 ; pixel p = (b, h, w) flattened NHW; z is NCHW
__global__ void t1_kernel(const float* __restrict__ z) {
    int p = blockIdx.x * blockDim.x + threadIdx.x;
    int b = p >> 12, hw = p & 4095;
    const float* base = z + (size_t)b * (size_t)(Dd * HW) + hw;
    double s = 0.0;
    #pragma unroll 8
    for (int d = 0; d < Dd; d++) { double v = (double)base[(size_t)d * HW]; s += v * v; }
    g_t1[p] = (float)s;
}

// ---------------------------------------------------------------------------
// Fused GEMM + argmin.
// Block tile: 128 pixels x 128 codes, D chunked by 16. 256 threads, 8x8/thread.
// Score (faithful to reference rounding): d = fl( fl(t1 + t2[k]) - 2*dot )
constexpr int BM = 128, BN = 128, BK = 16, TM = 8, TN = 8;

__global__ __launch_bounds__(256, 2)
void argmin_kernel(const float* __restrict__ z, const float* __restrict__ emb) {
    __shared__ float As[BK][BM];       // z tile, [kd][m]
    __shared__ float Bs[BK][BN + 4];   // emb tile, [kd][n], padded
    __shared__ float sv[BM][17];
    __shared__ int   sk[BM][17];

    const int tid = threadIdx.x;          // 0..255
    const int tx  = tid & 15;             // code group
    const int ty  = tid >> 4;             // pixel group
    const int m0  = blockIdx.x * BM;      // 128 pixels, contiguous hw within one image
    const int b   = m0 >> 12;
    const int hw0 = m0 & 4095;
    const float* zbase = z + (size_t)b * (size_t)(Dd * HW) + hw0;

    float bestv[TM];
    int   bestk[TM];
    float t1r[TM];
    #pragma unroll
    for (int i = 0; i < TM; i++) {
        bestv[i] = 3.4e38f;
        bestk[i] = 0;
        t1r[i]   = g_t1[m0 + ty * TM + i];
    }

    for (int n0 = 0; n0 < KK; n0 += BN) {
        float acc[TM][TN];
        #pragma unroll
        for (int i = 0; i < TM; i++)
            #pragma unroll
            for (int j = 0; j < TN; j++) acc[i][j] = 0.0f;

        for (int d0 = 0; d0 < Dd; d0 += BK) {
            // load z tile: 2048 elems, coalesced along m
            #pragma unroll
            for (int i = 0; i < 8; i++) {
                int e  = tid + i * 256;
                int kd = e >> 7;          // /128
                int m  = e & 127;
                As[kd][m] = zbase[(size_t)(d0 + kd) * HW + m];
            }
            // load emb tile via float4 (emb row-major [K, D])
            #pragma unroll
            for (int i = 0; i < 2; i++) {
                int e  = tid + i * 256;   // 0..511
                int n  = e >> 2;
                int kq = (e & 3) * 4;
                float4 v = *(const float4*)(emb + (size_t)(n0 + n) * Dd + d0 + kq);
                Bs[kq + 0][n] = v.x;
                Bs[kq + 1][n] = v.y;
                Bs[kq + 2][n] = v.z;
                Bs[kq + 3][n] = v.w;
            }
            __syncthreads();

            #pragma unroll
            for (int kd = 0; kd < BK; kd++) {
                float4 a0 = *(const float4*)&As[kd][ty * TM];
                float4 a1 = *(const float4*)&As[kd][ty * TM + 4];
                float4 b0 = *(const float4*)&Bs[kd][tx * TN];
                float4 b1 = *(const float4*)&Bs[kd][tx * TN + 4];
                float av[TM] = {a0.x, a0.y, a0.z, a0.w, a1.x, a1.y, a1.z, a1.w};
                float bv[TN] = {b0.x, b0.y, b0.z, b0.w, b1.x, b1.y, b1.z, b1.w};
                #pragma unroll
                for (int i = 0; i < TM; i++)
                    #pragma unroll
                    for (int j = 0; j < TN; j++)
                        acc[i][j] = fmaf(av[i], bv[j], acc[i][j]);
            }
            __syncthreads();
        }

        // epilogue: faithful rounding order: (t1 + t2) - 2*dot ; ascending k keeps
        // lowest index on exact ties (matches jnp.argmin)
        #pragma unroll
        for (int j = 0; j < TN; j++) {
            int kidx  = n0 + tx * TN + j;
            float t2v = g_t2[kidx];
            #pragma unroll
            for (int i = 0; i < TM; i++) {
                float dval = __fadd_rn(__fadd_rn(t1r[i], t2v), -2.0f * acc[i][j]);
                if (dval < bestv[i]) { bestv[i] = dval; bestk[i] = kidx; }
            }
        }
    }

    // cross-thread (tx) reduction per pixel; tx ascending -> ascending k ranges,
    // tie clause keeps lowest index
    #pragma unroll
    for (int i = 0; i < TM; i++) {
        sv[ty * TM + i][tx] = bestv[i];
        sk[ty * TM + i][tx] = bestk[i];
    }
    __syncthreads();
    if (tid < BM) {
        float bv = sv[tid][0];
        int   bk = sk[tid][0];
        #pragma unroll
        for (int t = 1; t < 16; t++) {
            float v = sv[tid][t];
            int   kk2 = sk[tid][t];
            if (v < bv || (v == bv && kk2 < bk)) { bv = v; bk = kk2; }
        }
        g_idx[m0 + tid] = bk;
    }
}

// ---------------------------------------------------------------------------
// Gather z_q = emb[idx], write NCHW output (coalesced along w), accumulate loss
// partial per block; optionally emit indices as float.
__global__ void out_kernel(const float* __restrict__ z, const float* __restrict__ emb,
                           float* __restrict__ out, float* __restrict__ idx_out,
                           int has_idx) {
    __shared__ int   sidx[32];
    __shared__ float red[256];
    const int tid = threadIdx.x;
    const int p0  = blockIdx.x * 32;
    const int b   = p0 >> 12;
    const int hw0 = p0 & 4095;

    if (tid < 32) {
        int iv = g_idx[p0 + tid];
        sidx[tid] = iv;
        if (has_idx) idx_out[p0 + tid] = (float)iv;
    }
    __syncthreads();

    const int p  = tid & 31;
    const int dl = tid >> 5;                   // 0..7
    const float* zb   = z   + (size_t)b * (size_t)(Dd * HW) + hw0 + p;
    float*       ob   = out + (size_t)b * (size_t)(Dd * HW) + hw0 + p;
    const float* erow = emb + (size_t)sidx[p] * Dd;

    float acc = 0.0f;
    #pragma unroll
    for (int db = 0; db < 32; db++) {
        int d = db * 8 + dl;
        float e  = erow[d];
        float zv = zb[(size_t)d * HW];
        ob[(size_t)d * HW] = e;
        float df = e - zv;
        acc = fmaf(df, df, acc);
    }

    red[tid] = acc;
    __syncthreads();
    for (int s = 128; s > 0; s >>= 1) {
        if (tid < s) red[tid] += red[tid + s];
        __syncthreads();
    }
    if (tid == 0) g_part[blockIdx.x] = red[0];
}

// Deterministic final loss reduction: loss = BETA * mean((z_q - z)^2)
__global__ void loss_kernel(float* __restrict__ out_loss) {
    __shared__ double red[256];
    const int tid = threadIdx.x;
    double s = 0.0;
    #pragma unroll
    for (int i = 0; i < 8; i++) s += (double)g_part[tid * 8 + i];
    red[tid] = s;
    __syncthreads();
    for (int st = 128; st > 0; st >>= 1) {
        if (tid < st) red[tid] += red[tid + st];
        __syncthreads();
    }
    if (tid == 0) *out_loss = (float)(0.25 * (red[0] / (double)NOUT));
}

// ---------------------------------------------------------------------------
extern "C" void kernel_launch(void* const* d_in, const int* in_sizes, int n_in,
                              void* d_out, int out_size) {
    const float* z   = (const float*)d_in[0];
    const float* emb = (const float*)d_in[1];
    float* out = (float*)d_out;

    const int has_idx  = (out_size >= NOUT + NPIX) ? 1 : 0;
    const int has_loss = (out_size >= NOUT + NPIX + 1) ? 1 : 0;

    t2_kernel<<<KK / 256, 256>>>(emb);
    t1_kernel<<<NPIX / 256, 256>>>(z);
    argmin_kernel<<<NPIX / BM, 256>>>(z, emb);
    out_kernel<<<NPIX / 32, 256>>>(z, emb, out, out + NOUT, has_idx);
    if (has_loss) loss_kernel<<<1, 256>>>(out + NOUT + NPIX);
}

// round 2
// speedup vs baseline: 1.0182x; 1.0182x over previous
#include <cuda_runtime.h>

// Problem constants
constexpr int Dd   = 256;       // latent dim
constexpr int HW   = 4096;      // 64*64
constexpr int NPIX = 65536;     // 16*64*64
constexpr int KK   = 1024;      // codebook size
constexpr int NOUT = 16777216;  // 16*256*64*64

typedef unsigned long long u64;

__device__ __forceinline__ u64 pack_dup(float x) {
    u64 r; asm("mov.b64 %0, {%1, %1};" : "=l"(r) : "f"(x)); return r;
}
__device__ __forceinline__ u64 ffma2(u64 a, u64 b, u64 c) {
    u64 d; asm("fma.rn.f32x2 %0, %1, %2, %3;" : "=l"(d) : "l"(a), "l"(b), "l"(c)); return d;
}
__device__ __forceinline__ void unpack2(u64 v, float& lo, float& hi) {
    asm("mov.b64 {%0, %1}, %2;" : "=f"(lo), "=f"(hi) : "l"(v));
}

// Scratch (static device globals; no allocations allowed)
__device__ float g_t1[NPIX];     // ||z_p||^2
__device__ float g_t2[KK];       // ||e_k||^2
__device__ int   g_idx[NPIX];    // argmin indices
__device__ float g_part[NPIX / 32]; // per-block loss partials (2048)

// ---------------------------------------------------------------------------
// ||e_k||^2
__global__ void t2_kernel(const float* __restrict__ emb) {
    int k = blockIdx.x * blockDim.x + threadIdx.x;
    if (k < KK) {
        const float* row = emb + (size_t)k * Dd;
        double s = 0.0;
        #pragma unroll 8
        for (int d = 0; d < Dd; d++) { double v = (double)row[d]; s += v * v; }
        g_t2[k] = (float)s;
    }
}

// ||z_p||^2 ; pixel p = (b, h, w) flattened NHW; z is NCHW
__global__ void t1_kernel(const float* __restrict__ z) {
    int p = blockIdx.x * blockDim.x + threadIdx.x;
    int b = p >> 12, hw = p & 4095;
    const float* base = z + (size_t)b * (size_t)(Dd * HW) + hw;
    double s = 0.0;
    #pragma unroll 8
    for (int d = 0; d < Dd; d++) { double v = (double)base[(size_t)d * HW]; s += v * v; }
    g_t1[p] = (float)s;
}

// ---------------------------------------------------------------------------
// Fused GEMM + argmin with packed f32x2 FFMA.
// Block tile: 128 pixels x 128 codes, D chunked by 16. 256 threads, 8x8/thread.
// Per-lane arithmetic bit-identical to scalar fmaf version.
constexpr int BM = 128, BN = 128, BK = 16, TM = 8, TN = 8, TN2 = TN / 2;

__global__ __launch_bounds__(256, 2)
void argmin_kernel(const float* __restrict__ z, const float* __restrict__ emb) {
    __shared__ float As[BK][BM];       // z tile, [kd][m]
    __shared__ float Bs[BK][BN + 4];   // emb tile, [kd][n], padded (row = 528B, 16B-aligned)
    __shared__ float sv[BM][17];
    __shared__ int   sk[BM][17];

    const int tid = threadIdx.x;          // 0..255
    const int tx  = tid & 15;             // code group
    const int ty  = tid >> 4;             // pixel group
    const int m0  = blockIdx.x * BM;      // 128 pixels, contiguous hw within one image
    const int b   = m0 >> 12;
    const int hw0 = m0 & 4095;
    const float* zbase = z + (size_t)b * (size_t)(Dd * HW) + hw0;

    float bestv[TM];
    int   bestk[TM];
    float t1r[TM];
    #pragma unroll
    for (int i = 0; i < TM; i++) {
        bestv[i] = 3.4e38f;
        bestk[i] = 0;
        t1r[i]   = g_t1[m0 + ty * TM + i];
    }

    for (int n0 = 0; n0 < KK; n0 += BN) {
        u64 acc[TM][TN2];
        #pragma unroll
        for (int i = 0; i < TM; i++)
            #pragma unroll
            for (int j = 0; j < TN2; j++) acc[i][j] = 0ull;

        for (int d0 = 0; d0 < Dd; d0 += BK) {
            // load z tile: 2048 elems, coalesced along m
            #pragma unroll
            for (int i = 0; i < 8; i++) {
                int e  = tid + i * 256;
                int kd = e >> 7;          // /128
                int m  = e & 127;
                As[kd][m] = zbase[(size_t)(d0 + kd) * HW + m];
            }
            // load emb tile via float4 (emb row-major [K, D])
            #pragma unroll
            for (int i = 0; i < 2; i++) {
                int e  = tid + i * 256;   // 0..511
                int n  = e >> 2;
                int kq = (e & 3) * 4;
                float4 v = *(const float4*)(emb + (size_t)(n0 + n) * Dd + d0 + kq);
                Bs[kq + 0][n] = v.x;
                Bs[kq + 1][n] = v.y;
                Bs[kq + 2][n] = v.z;
                Bs[kq + 3][n] = v.w;
            }
            __syncthreads();

            #pragma unroll
            for (int kd = 0; kd < BK; kd++) {
                // B pairs: natural 64-bit pairs from smem (two LDS.128)
                const u64* brow = (const u64*)&Bs[kd][tx * TN];
                u64 bp0 = brow[0], bp1 = brow[1], bp2 = brow[2], bp3 = brow[3];
                // A values, duplicated into both f32x2 lanes
                float4 a0 = *(const float4*)&As[kd][ty * TM];
                float4 a1 = *(const float4*)&As[kd][ty * TM + 4];
                float av[TM] = {a0.x, a0.y, a0.z, a0.w, a1.x, a1.y, a1.z, a1.w};
                #pragma unroll
                for (int i = 0; i < TM; i++) {
                    u64 ad = pack_dup(av[i]);
                    acc[i][0] = ffma2(ad, bp0, acc[i][0]);
                    acc[i][1] = ffma2(ad, bp1, acc[i][1]);
                    acc[i][2] = ffma2(ad, bp2, acc[i][2]);
                    acc[i][3] = ffma2(ad, bp3, acc[i][3]);
                }
            }
            __syncthreads();
        }

        // epilogue: faithful rounding order: (t1 + t2) - 2*dot ; ascending k keeps
        // lowest index on exact ties (matches jnp.argmin)
        #pragma unroll
        for (int i = 0; i < TM; i++) {
            #pragma unroll
            for (int j2 = 0; j2 < TN2; j2++) {
                float slo, shi;
                unpack2(acc[i][j2], slo, shi);
                int klo = n0 + tx * TN + j2 * 2;
                float t2lo = g_t2[klo];
                float t2hi = g_t2[klo + 1];
                float dlo = __fadd_rn(__fadd_rn(t1r[i], t2lo), -2.0f * slo);
                if (dlo < bestv[i]) { bestv[i] = dlo; bestk[i] = klo; }
                float dhi = __fadd_rn(__fadd_rn(t1r[i], t2hi), -2.0f * shi);
                if (dhi < bestv[i]) { bestv[i] = dhi; bestk[i] = klo + 1; }
            }
        }
    }

    // cross-thread (tx) reduction per pixel; tx ascending -> ascending k ranges,
    // tie clause keeps lowest index
    #pragma unroll
    for (int i = 0; i < TM; i++) {
        sv[ty * TM + i][tx] = bestv[i];
        sk[ty * TM + i][tx] = bestk[i];
    }
    __syncthreads();
    if (tid < BM) {
        float bv = sv[tid][0];
        int   bk = sk[tid][0];
        #pragma unroll
        for (int t = 1; t < 16; t++) {
            float v = sv[tid][t];
            int   kk2 = sk[tid][t];
            if (v < bv || (v == bv && kk2 < bk)) { bv = v; bk = kk2; }
        }
        g_idx[m0 + tid] = bk;
    }
}

// ---------------------------------------------------------------------------
// Gather z_q = emb[idx], write NCHW output (coalesced along w), accumulate loss
// partial per block; optionally emit indices as float.
__global__ void out_kernel(const float* __restrict__ z, const float* __restrict__ emb,
                           float* __restrict__ out, float* __restrict__ idx_out,
                           int has_idx) {
    __shared__ int   sidx[32];
    __shared__ float red[256];
    const int tid = threadIdx.x;
    const int p0  = blockIdx.x * 32;
    const int b   = p0 >> 12;
    const int hw0 = p0 & 4095;

    if (tid < 32) {
        int iv = g_idx[p0 + tid];
        sidx[tid] = iv;
        if (has_idx) idx_out[p0 + tid] = (float)iv;
    }
    __syncthreads();

    const int p  = tid & 31;
    const int dl = tid >> 5;                   // 0..7
    const float* zb   = z   + (size_t)b * (size_t)(Dd * HW) + hw0 + p;
    float*       ob   = out + (size_t)b * (size_t)(Dd * HW) + hw0 + p;
    const float* erow = emb + (size_t)sidx[p] * Dd;

    float acc = 0.0f;
    #pragma unroll
    for (int db = 0; db < 32; db++) {
        int d = db * 8 + dl;
        float e  = erow[d];
        float zv = zb[(size_t)d * HW];
        ob[(size_t)d * HW] = e;
        float df = e - zv;
        acc = fmaf(df, df, acc);
    }

    red[tid] = acc;
    __syncthreads();
    for (int s = 128; s > 0; s >>= 1) {
        if (tid < s) red[tid] += red[tid + s];
        __syncthreads();
    }
    if (tid == 0) g_part[blockIdx.x] = red[0];
}

// Deterministic final loss reduction: loss = BETA * mean((z_q - z)^2)
__global__ void loss_kernel(float* __restrict__ out_loss) {
    __shared__ double red[256];
    const int tid = threadIdx.x;
    double s = 0.0;
    #pragma unroll
    for (int i = 0; i < 8; i++) s += (double)g_part[tid * 8 + i];
    red[tid] = s;
    __syncthreads();
    for (int st = 128; st > 0; st >>= 1) {
        if (tid < st) red[tid] += red[tid + st];
        __syncthreads();
    }
    if (tid == 0) *out_loss = (float)(0.25 * (red[0] / (double)NOUT));
}

// ---------------------------------------------------------------------------
extern "C" void kernel_launch(void* const* d_in, const int* in_sizes, int n_in,
                              void* d_out, int out_size) {
    const float* z   = (const float*)d_in[0];
    const float* emb = (const float*)d_in[1];
    float* out = (float*)d_out;

    const int has_idx  = (out_size >= NOUT + NPIX) ? 1 : 0;
    const int has_loss = (out_size >= NOUT + NPIX + 1) ? 1 : 0;

    t2_kernel<<<KK / 256, 256>>>(emb);
    t1_kernel<<<NPIX / 256, 256>>>(z);
    argmin_kernel<<<NPIX / BM, 256>>>(z, emb);
    out_kernel<<<NPIX / 32, 256>>>(z, emb, out, out + NOUT, has_idx);
    if (has_loss) loss_kernel<<<1, 256>>>(out + NOUT + NPIX);
}

// round 4
// speedup vs baseline: 1.8268x; 1.7941x over previous
#include <cuda_runtime.h>
#include <cuda_bf16.h>
#include <cstdint>

// Problem constants
constexpr int Dd   = 256;       // latent dim
constexpr int HW   = 4096;      // 64*64
constexpr int NPIX = 65536;     // 16*64*64
constexpr int KK   = 1024;      // codebook size
constexpr int NOUT = 16777216;  // 16*256*64*64

// ---------------------------------------------------------------------------
// Scratch (static device globals; no allocations allowed)
__device__ float g_t1[NPIX];
__device__ float g_t2[KK];
__device__ int   g_idx[NPIX];
__device__ float g_part[NPIX / 32];

// A split levels, bf16x2-packed u32: [level][pixel][128]
__device__ unsigned g_a[2][(size_t)NPIX * 128];
// B split levels, bf16: [level][k][256]
__device__ unsigned short g_b[2][(size_t)KK * Dd];

// ---------------------------------------------------------------------------
// PTX helpers (all arch-agnostic: sm_80+ ISA, safe for compute_103 virtual arch)
__device__ __forceinline__ uint32_t smem_u32(const void* p) {
    uint32_t a;
    asm("{ .reg .u64 t; cvta.to.shared.u64 t, %1; cvt.u32.u64 %0, t; }" : "=r"(a) : "l"(p));
    return a;
}
__device__ __forceinline__ void ldsm4(uint32_t addr, unsigned& r0, unsigned& r1,
                                      unsigned& r2, unsigned& r3) {
    asm volatile("ldmatrix.sync.aligned.m8n8.x4.shared.b16 {%0,%1,%2,%3}, [%4];"
        : "=r"(r0), "=r"(r1), "=r"(r2), "=r"(r3) : "r"(addr));
}
__device__ __forceinline__ void mma16816(float* d, const unsigned* a, const unsigned* b) {
    asm volatile("mma.sync.aligned.m16n8k16.row.col.f32.bf16.bf16.f32 "
        "{%0,%1,%2,%3}, {%4,%5,%6,%7}, {%8,%9}, {%0,%1,%2,%3};"
        : "+f"(d[0]), "+f"(d[1]), "+f"(d[2]), "+f"(d[3])
        : "r"(a[0]), "r"(a[1]), "r"(a[2]), "r"(a[3]), "r"(b[0]), "r"(b[1]));
}
__device__ __forceinline__ void cp16(uint32_t dst, const void* src) {
    asm volatile("cp.async.cg.shared.global [%0], [%1], 16;" :: "r"(dst), "l"(src));
}
#define CP_COMMIT() asm volatile("cp.async.commit_group;" ::: "memory")

// ---------------------------------------------------------------------------
// ||e_k||^2 (fp64-accumulated, rounded to f32 — matches reference quantization)
__global__ void t2_kernel(const float* __restrict__ emb) {
    int k = blockIdx.x * blockDim.x + threadIdx.x;
    if (k < KK) {
        const float* row = emb + (size_t)k * Dd;
        double s = 0.0;
        #pragma unroll 8
        for (int d = 0; d < Dd; d++) { double v = (double)row[d]; s += v * v; }
        g_t2[k] = (float)s;
    }
}

// ---------------------------------------------------------------------------
__device__ __forceinline__ void split2(float v, unsigned short& s0, unsigned short& s1) {
    __nv_bfloat16 b0 = __float2bfloat16_rn(v);
    float r = v - __bfloat162float(b0);
    __nv_bfloat16 b1 = __float2bfloat16_rn(r);
    s0 = __bfloat16_as_ushort(b0);
    s1 = __bfloat16_as_ushort(b1);
}

// A prep: z NCHW -> g_a[level][p][d] bf16x2-packed; also fused ||z_p||^2 (fp64).
__global__ void prep_a_kernel(const float* __restrict__ z) {
    __shared__ float tile[32][128];
    __shared__ double t1part[2][128];
    const int t   = threadIdx.x;           // 0..255
    const int blk = blockIdx.x;            // 0..511
    const int b   = blk >> 5;
    const int hw0 = (blk & 31) * 128;
    const float* zb = z + (size_t)b * (size_t)(Dd * HW) + hw0;

    const int pl = t & 127;
    const int h  = t >> 7;                 // 0/1
    double t1acc = 0.0;

    for (int d0 = 0; d0 < Dd; d0 += 32) {
        __syncthreads();
        #pragma unroll
        for (int r = 0; r < 16; r++) {
            int e = t + r * 256;
            int dl = e >> 7, hwi = e & 127;
            tile[dl][hwi] = zb[(size_t)(d0 + dl) * HW + hwi];
        }
        __syncthreads();
        const size_t p = (size_t)b * HW + hw0 + pl;
        unsigned o0[8], o1[8];
        #pragma unroll
        for (int u = 0; u < 8; u++) {
            int dp = h * 8 + u;
            float f0 = tile[2 * dp][pl];
            float f1 = tile[2 * dp + 1][pl];
            t1acc += (double)f0 * f0 + (double)f1 * f1;
            unsigned short a0, a1, c0, c1;
            split2(f0, a0, a1);
            split2(f1, c0, c1);
            o0[u] = (unsigned)a0 | ((unsigned)c0 << 16);
            o1[u] = (unsigned)a1 | ((unsigned)c1 << 16);
        }
        const size_t base = p * 128 + (d0 >> 1) + h * 8;
        *(uint4*)&g_a[0][base]     = *(uint4*)&o0[0];
        *(uint4*)&g_a[0][base + 4] = *(uint4*)&o0[4];
        *(uint4*)&g_a[1][base]     = *(uint4*)&o1[0];
        *(uint4*)&g_a[1][base + 4] = *(uint4*)&o1[4];
    }
    t1part[h][pl] = t1acc;
    __syncthreads();
    if (h == 0)
        g_t1[(size_t)b * HW + hw0 + pl] = (float)(t1part[0][pl] + t1part[1][pl]);
}

// B prep: elementwise split of emb into 2 bf16 levels
__global__ void prep_b_kernel(const float* __restrict__ emb) {
    int i = blockIdx.x * blockDim.x + threadIdx.x;   // 0..262143
    float v = emb[i];
    unsigned short s0, s1;
    split2(v, s0, s1);
    g_b[0][i] = s0;
    g_b[1][i] = s1;
}

// ---------------------------------------------------------------------------
// Fused split-GEMM + argmin on HMMA (mma.sync m16n8k16 bf16).
// CTA: 128 pixels x 1024 codes. 256 threads = 8 warps (2 x 4 grid, warp tile 64x32).
// A (both levels) resident in SMEM, padded rows; B double-buffered cp.async chunks.
constexpr int AS_OFF   = 0;
constexpr int AS_LEV   = 128 * 528;            // 67584
constexpr int BS_OFF   = 2 * AS_LEV;           // 135168
constexpr int BS_BUF   = 128 * 272;            // 34816
constexpr int T2_OFF   = BS_OFF + 2 * BS_BUF;  // 204800
constexpr int REDV_OFF = T2_OFF + 4096;        // 208896
constexpr int REDK_OFF = REDV_OFF + 2048;      // 210944
constexpr int SM_TOTAL = REDK_OFF + 2048;      // 212992

constexpr int NCHUNK = 48;  // 8 cb x 3 passes x 2 k-halves

__global__ __launch_bounds__(256, 1)
void argmin_mma_kernel() {
    extern __shared__ char smem[];
    const uint32_t sbase = smem_u32(smem);
    const int tid   = threadIdx.x;
    const int lane  = tid & 31;
    const int wid   = tid >> 5;
    const int wm    = wid >> 2;          // 0..1
    const int wn    = wid & 3;           // 0..3
    const int m0    = blockIdx.x * 128;

    // t2 -> smem
    #pragma unroll
    for (int i = 0; i < 4; i++)
        ((float*)(smem + T2_OFF))[tid + i * 256] = g_t2[tid + i * 256];

    // A (2 levels) -> padded smem rows (row stride 528B; 528 % 128 = 16 -> ldmatrix conflict-free)
    #pragma unroll
    for (int lev = 0; lev < 2; lev++) {
        const uint4* src = (const uint4*)&g_a[lev][(size_t)m0 * 128];
        #pragma unroll 4
        for (int i = tid; i < 4096; i += 256) {
            int row = i >> 5, c = i & 31;
            *(uint4*)(smem + AS_OFF + lev * AS_LEV + row * 528 + c * 16) = src[(size_t)row * 32 + c];
        }
    }

    // per-thread t1 for owned rows
    const int g = lane >> 2;
    float t1r[8];
    #pragma unroll
    for (int im = 0; im < 4; im++) {
        t1r[im * 2]     = g_t1[m0 + wm * 64 + im * 16 + g];
        t1r[im * 2 + 1] = g_t1[m0 + wm * 64 + im * 16 + g + 8];
    }

    // lane-dependent ldmatrix offsets
    const int a_kadd = (lane >> 4) * 8;
    const int b_kadd = ((lane >> 3) & 1) * 8;
    uint32_t aRow[4], bRow[2];
    #pragma unroll
    for (int im = 0; im < 4; im++)
        aRow[im] = (uint32_t)((wm * 64 + im * 16 + (lane & 7) + ((lane >> 3) & 1) * 8) * 528);
    #pragma unroll
    for (int j2 = 0; j2 < 2; j2++)
        bRow[j2] = (uint32_t)((wn * 32 + j2 * 16 + (lane & 7) + ((lane >> 4) & 1) * 8) * 272);

    float acc[4][4][4];
    #pragma unroll
    for (int im = 0; im < 4; im++)
        #pragma unroll
        for (int jn = 0; jn < 4; jn++)
            #pragma unroll
            for (int c = 0; c < 4; c++) acc[im][jn][c] = 0.0f;

    float bestv[8];
    int   bestk[8];
    #pragma unroll
    for (int r = 0; r < 8; r++) { bestv[r] = 3.4e38f; bestk[r] = 0; }

    __syncthreads();

    // cp.async chunk issue: chunk i -> (cb=i/6, pass=(i%6)/2, kc=i&1)
    auto issue = [&](int i) {
        int cb = i / 6, r6 = i % 6, pass = r6 >> 1, kc = r6 & 1;
        int lev_b = (pass == 2) ? 1 : 0;
        int d0 = kc * 128;
        const char* srcbase = (const char*)&g_b[lev_b][((size_t)(cb * 128)) * Dd + d0];
        uint32_t dstbase = sbase + BS_OFF + (uint32_t)(i & 1) * BS_BUF;
        #pragma unroll
        for (int j = 0; j < 8; j++) {
            int f = j * 256 + tid;
            int n = f >> 4, seg = f & 15;
            cp16(dstbase + (uint32_t)n * 272 + seg * 16,
                 srcbase + (size_t)n * (Dd * 2) + seg * 16);
        }
        CP_COMMIT();
    };

    issue(0);

    for (int i = 0; i < NCHUNK; i++) {
        if (i + 1 < NCHUNK) {
            issue(i + 1);
            asm volatile("cp.async.wait_group 1;" ::: "memory");
        } else {
            asm volatile("cp.async.wait_group 0;" ::: "memory");
        }
        __syncthreads();

        const int cb = i / 6, r6 = i % 6, pass = r6 >> 1, kc = r6 & 1;
        const int lev_a = (pass == 1) ? 1 : 0;
        const int d0 = kc * 128;
        const uint32_t Abase = sbase + AS_OFF + (uint32_t)lev_a * AS_LEV;
        const uint32_t Bbase = sbase + BS_OFF + (uint32_t)(i & 1) * BS_BUF;

        #pragma unroll
        for (int k16 = 0; k16 < 8; k16++) {
            const int kl = k16 * 16;
            unsigned af[4][4], bfr[4][2];
            #pragma unroll
            for (int im = 0; im < 4; im++)
                ldsm4(Abase + aRow[im] + (uint32_t)(d0 + kl + a_kadd) * 2,
                      af[im][0], af[im][1], af[im][2], af[im][3]);
            #pragma unroll
            for (int j2 = 0; j2 < 2; j2++) {
                unsigned r0, r1, r2, r3;
                ldsm4(Bbase + bRow[j2] + (uint32_t)(kl + b_kadd) * 2, r0, r1, r2, r3);
                bfr[j2 * 2][0] = r0;     bfr[j2 * 2][1] = r1;
                bfr[j2 * 2 + 1][0] = r2; bfr[j2 * 2 + 1][1] = r3;
            }
            #pragma unroll
            for (int im = 0; im < 4; im++)
                #pragma unroll
                for (int jn = 0; jn < 4; jn++)
                    mma16816(acc[im][jn], af[im], bfr[jn]);
        }
        __syncthreads();   // protect buffer reuse by issue(i+2)

        if (r6 == 5) {
            // epilogue for code block cb: bit-faithful score + per-row argmin
            const float* t2s = (const float*)(smem + T2_OFF);
            #pragma unroll
            for (int im = 0; im < 4; im++) {
                #pragma unroll
                for (int jn = 0; jn < 4; jn++) {
                    int kbase = cb * 128 + wn * 32 + jn * 8 + (lane & 3) * 2;
                    float t2a = t2s[kbase], t2b = t2s[kbase + 1];
                    float d0v = __fadd_rn(__fadd_rn(t1r[im * 2], t2a), -2.0f * acc[im][jn][0]);
                    float d1v = __fadd_rn(__fadd_rn(t1r[im * 2], t2b), -2.0f * acc[im][jn][1]);
                    if (d0v < bestv[im * 2]) { bestv[im * 2] = d0v; bestk[im * 2] = kbase; }
                    if (d1v < bestv[im * 2]) { bestv[im * 2] = d1v; bestk[im * 2] = kbase + 1; }
                    float d2v = __fadd_rn(__fadd_rn(t1r[im * 2 + 1], t2a), -2.0f * acc[im][jn][2]);
                    float d3v = __fadd_rn(__fadd_rn(t1r[im * 2 + 1], t2b), -2.0f * acc[im][jn][3]);
                    if (d2v < bestv[im * 2 + 1]) { bestv[im * 2 + 1] = d2v; bestk[im * 2 + 1] = kbase; }
                    if (d3v < bestv[im * 2 + 1]) { bestv[im * 2 + 1] = d3v; bestk[im * 2 + 1] = kbase + 1; }
                    #pragma unroll
                    for (int c = 0; c < 4; c++) acc[im][jn][c] = 0.0f;
                }
            }
        }
    }

    // quad reduction (lanes in same group of 4 hold same rows, different cols)
    #pragma unroll
    for (int off = 1; off <= 2; off <<= 1) {
        #pragma unroll
        for (int r = 0; r < 8; r++) {
            float ov = __shfl_xor_sync(0xffffffffu, bestv[r], off);
            int   ok = __shfl_xor_sync(0xffffffffu, bestk[r], off);
            if (ov < bestv[r] || (ov == bestv[r] && ok < bestk[r])) {
                bestv[r] = ov; bestk[r] = ok;
            }
        }
    }
    float* redv = (float*)(smem + REDV_OFF);
    int*   redk = (int*)(smem + REDK_OFF);
    if ((lane & 3) == 0) {
        #pragma unroll
        for (int im = 0; im < 4; im++) {
            #pragma unroll
            for (int hh = 0; hh < 2; hh++) {
                int row = wm * 64 + im * 16 + g + hh * 8;
                redv[row * 4 + wn] = bestv[im * 2 + hh];
                redk[row * 4 + wn] = bestk[im * 2 + hh];
            }
        }
    }
    __syncthreads();
    if (tid < 128) {
        float bv = redv[tid * 4];
        int   bk = redk[tid * 4];
        #pragma unroll
        for (int w = 1; w < 4; w++) {
            float v = redv[tid * 4 + w];
            int   k = redk[tid * 4 + w];
            if (v < bv || (v == bv && k < bk)) { bv = v; bk = k; }
        }
        g_idx[m0 + tid] = bk;
    }
}

// ---------------------------------------------------------------------------
// Gather z_q = emb[idx], write NCHW output, loss partials, indices as float.
__global__ void out_kernel(const float* __restrict__ z, const float* __restrict__ emb,
                           float* __restrict__ out, float* __restrict__ idx_out,
                           int has_idx) {
    __shared__ int   sidx[32];
    __shared__ float red[256];
    const int tid = threadIdx.x;
    const int p0  = blockIdx.x * 32;
    const int b   = p0 >> 12;
    const int hw0 = p0 & 4095;

    if (tid < 32) {
        int iv = g_idx[p0 + tid];
        sidx[tid] = iv;
        if (has_idx) idx_out[p0 + tid] = (float)iv;
    }
    __syncthreads();

    const int p  = tid & 31;
    const int dl = tid >> 5;
    const float* zb   = z   + (size_t)b * (size_t)(Dd * HW) + hw0 + p;
    float*       ob   = out + (size_t)b * (size_t)(Dd * HW) + hw0 + p;
    const float* erow = emb + (size_t)sidx[p] * Dd;

    float acc = 0.0f;
    #pragma unroll
    for (int db = 0; db < 32; db++) {
        int d = db * 8 + dl;
        float e  = erow[d];
        float zv = zb[(size_t)d * HW];
        ob[(size_t)d * HW] = e;
        float df = e - zv;
        acc = fmaf(df, df, acc);
    }

    red[tid] = acc;
    __syncthreads();
    for (int s = 128; s > 0; s >>= 1) {
        if (tid < s) red[tid] += red[tid + s];
        __syncthreads();
    }
    if (tid == 0) g_part[blockIdx.x] = red[0];
}

__global__ void loss_kernel(float* __restrict__ out_loss) {
    __shared__ double red[256];
    const int tid = threadIdx.x;
    double s = 0.0;
    #pragma unroll
    for (int i = 0; i < 8; i++) s += (double)g_part[tid * 8 + i];
    red[tid] = s;
    __syncthreads();
    for (int st = 128; st > 0; st >>= 1) {
        if (tid < st) red[tid] += red[tid + st];
        __syncthreads();
    }
    if (tid == 0) *out_loss = (float)(0.25 * (red[0] / (double)NOUT));
}

// ---------------------------------------------------------------------------
extern "C" void kernel_launch(void* const* d_in, const int* in_sizes, int n_in,
                              void* d_out, int out_size) {
    const float* z   = (const float*)d_in[0];
    const float* emb = (const float*)d_in[1];
    float* out = (float*)d_out;

    const int has_idx  = (out_size >= NOUT + NPIX) ? 1 : 0;
    const int has_loss = (out_size >= NOUT + NPIX + 1) ? 1 : 0;

    static int attr_done = 0;
    if (!attr_done) {
        cudaFuncSetAttribute(argmin_mma_kernel,
                             cudaFuncAttributeMaxDynamicSharedMemorySize, SM_TOTAL);
        attr_done = 1;
    }

    prep_b_kernel<<<KK * Dd / 256, 256>>>(emb);
    prep_a_kernel<<<512, 256>>>(z);
    t2_kernel<<<KK / 256, 256>>>(emb);
    argmin_mma_kernel<<<512, 256, SM_TOTAL>>>();
    out_kernel<<<NPIX / 32, 256>>>(z, emb, out, out + NOUT, has_idx);
    if (has_loss) loss_kernel<<<1, 256>>>(out + NOUT + NPIX);
}

// round 7
// speedup vs baseline: 1.9177x; 1.0498x over previous
#include <cuda_runtime.h>
#include <cuda_bf16.h>
#include <cstdint>

// Problem constants
constexpr int Dd   = 256;       // latent dim
constexpr int HW   = 4096;      // 64*64
constexpr int NPIX = 65536;     // 16*64*64
constexpr int KK   = 1024;      // codebook size
constexpr int NOUT = 16777216;  // 16*256*64*64

// ---------------------------------------------------------------------------
// Scratch (static device globals; no allocations allowed)
__device__ float g_t1[NPIX];
__device__ float g_t2[KK];
__device__ int   g_idx[NPIX];
__device__ float g_part[NPIX / 32];

// A split levels, bf16x2-packed u32: [level][pixel][128]
__device__ unsigned g_a[2][(size_t)NPIX * 128];
// B split levels, bf16: [level][k][256]
__device__ unsigned short g_b[2][(size_t)KK * Dd];

// ---------------------------------------------------------------------------
// PTX helpers (arch-agnostic sm_80+ ISA only)
__device__ __forceinline__ uint32_t smem_u32(const void* p) {
    uint32_t a;
    asm("{ .reg .u64 t; cvta.to.shared.u64 t, %1; cvt.u32.u64 %0, t; }" : "=r"(a) : "l"(p));
    return a;
}
__device__ __forceinline__ void ldsm4(uint32_t addr, unsigned& r0, unsigned& r1,
                                      unsigned& r2, unsigned& r3) {
    asm volatile("ldmatrix.sync.aligned.m8n8.x4.shared.b16 {%0,%1,%2,%3}, [%4];"
        : "=r"(r0), "=r"(r1), "=r"(r2), "=r"(r3) : "r"(addr));
}
__device__ __forceinline__ void mma16816(float* d, const unsigned* a, const unsigned* b) {
    asm volatile("mma.sync.aligned.m16n8k16.row.col.f32.bf16.bf16.f32 "
        "{%0,%1,%2,%3}, {%4,%5,%6,%7}, {%8,%9}, {%0,%1,%2,%3};"
        : "+f"(d[0]), "+f"(d[1]), "+f"(d[2]), "+f"(d[3])
        : "r"(a[0]), "r"(a[1]), "r"(a[2]), "r"(a[3]), "r"(b[0]), "r"(b[1]));
}
__device__ __forceinline__ void cp16(uint32_t dst, const void* src) {
    asm volatile("cp.async.cg.shared.global [%0], [%1], 16;" :: "r"(dst), "l"(src));
}
#define CP_COMMIT() asm volatile("cp.async.commit_group;" ::: "memory")

// ---------------------------------------------------------------------------
// ||e_k||^2 (fp64-accumulated, rounded to f32)
__global__ void t2_kernel(const float* __restrict__ emb) {
    int k = blockIdx.x * blockDim.x + threadIdx.x;
    if (k < KK) {
        const float* row = emb + (size_t)k * Dd;
        double s = 0.0;
        #pragma unroll 8
        for (int d = 0; d < Dd; d++) { double v = (double)row[d]; s += v * v; }
        g_t2[k] = (float)s;
    }
}

// ---------------------------------------------------------------------------
__device__ __forceinline__ void split2(float v, unsigned short& s0, unsigned short& s1) {
    __nv_bfloat16 b0 = __float2bfloat16_rn(v);
    float r = v - __bfloat162float(b0);
    __nv_bfloat16 b1 = __float2bfloat16_rn(r);
    s0 = __bfloat16_as_ushort(b0);
    s1 = __bfloat16_as_ushort(b1);
}

// A prep: z NCHW -> g_a[level][p][d] bf16x2-packed; fused ||z_p||^2 (fp64).
__global__ void prep_a_kernel(const float* __restrict__ z) {
    __shared__ float tile[32][128];
    __shared__ double t1part[2][128];
    const int t   = threadIdx.x;
    const int blk = blockIdx.x;            // 0..511
    const int b   = blk >> 5;
    const int hw0 = (blk & 31) * 128;
    const float* zb = z + (size_t)b * (size_t)(Dd * HW) + hw0;

    const int pl = t & 127;
    const int h  = t >> 7;
    double t1acc = 0.0;

    for (int d0 = 0; d0 < Dd; d0 += 32) {
        __syncthreads();
        #pragma unroll
        for (int r = 0; r < 16; r++) {
            int e = t + r * 256;
            int dl = e >> 7, hwi = e & 127;
            tile[dl][hwi] = zb[(size_t)(d0 + dl) * HW + hwi];
        }
        __syncthreads();
        const size_t p = (size_t)b * HW + hw0 + pl;
        unsigned o0[8], o1[8];
        #pragma unroll
        for (int u = 0; u < 8; u++) {
            int dp = h * 8 + u;
            float f0 = tile[2 * dp][pl];
            float f1 = tile[2 * dp + 1][pl];
            t1acc += (double)f0 * f0 + (double)f1 * f1;
            unsigned short a0, a1, c0, c1;
            split2(f0, a0, a1);
            split2(f1, c0, c1);
            o0[u] = (unsigned)a0 | ((unsigned)c0 << 16);
            o1[u] = (unsigned)a1 | ((unsigned)c1 << 16);
        }
        const size_t base = p * 128 + (d0 >> 1) + h * 8;
        *(uint4*)&g_a[0][base]     = *(uint4*)&o0[0];
        *(uint4*)&g_a[0][base + 4] = *(uint4*)&o0[4];
        *(uint4*)&g_a[1][base]     = *(uint4*)&o1[0];
        *(uint4*)&g_a[1][base + 4] = *(uint4*)&o1[4];
    }
    t1part[h][pl] = t1acc;
    __syncthreads();
    if (h == 0)
        g_t1[(size_t)b * HW + hw0 + pl] = (float)(t1part[0][pl] + t1part[1][pl]);
}

// B prep: elementwise split of emb into 2 bf16 levels
__global__ void prep_b_kernel(const float* __restrict__ emb) {
    int i = blockIdx.x * blockDim.x + threadIdx.x;
    float v = emb[i];
    unsigned short s0, s1;
    split2(v, s0, s1);
    g_b[0][i] = s0;
    g_b[1][i] = s1;
}

// ---------------------------------------------------------------------------
// Fused split-GEMM + argmin on HMMA, fused 3-product k-slabs.
// CTA: 128 pixels x 1024 codes. 8 warps, grid 2(m) x 4(n), warp tile 64x64.
// Chunk: 256 codes x 32 k, BOTH levels interleaved (row = 64B lev0 | 64B lev1 | 16B pad).
// A (both levels) resident in SMEM (528B rows).
constexpr int AS_LEV   = 128 * 528;            // 67584
constexpr int BS_OFF   = 2 * AS_LEV;           // 135168
constexpr int BS_BUF   = 256 * 144;            // 36864
constexpr int T2_OFF   = BS_OFF + 2 * BS_BUF;  // 208896
constexpr int T1_OFF   = T2_OFF + 4096;        // 212992
constexpr int REDV_OFF = T1_OFF + 512;         // 213504
constexpr int REDK_OFF = REDV_OFF + 2048;      // 215552
constexpr int SM_TOTAL = REDK_OFF + 2048;      // 217600

constexpr int NCHUNK = 32;  // 4 cb (256 codes) x 8 kc (32 k)

__global__ __launch_bounds__(256, 1)
void argmin_mma_kernel() {
    extern __shared__ char smem[];
    const uint32_t sbase = smem_u32(smem);
    const int tid   = threadIdx.x;
    const int lane  = tid & 31;
    const int wid   = tid >> 5;
    const int wm    = wid >> 2;          // 0..1
    const int wn    = wid & 3;           // 0..3
    const int m0    = blockIdx.x * 128;

    // t2, t1 -> smem
    #pragma unroll
    for (int i = 0; i < 4; i++)
        ((float*)(smem + T2_OFF))[tid + i * 256] = g_t2[tid + i * 256];
    if (tid < 128) ((float*)(smem + T1_OFF))[tid] = g_t1[m0 + tid];

    // A (2 levels) -> padded smem rows (528B stride: conflict-free ldmatrix)
    #pragma unroll
    for (int lev = 0; lev < 2; lev++) {
        const uint4* src = (const uint4*)&g_a[lev][(size_t)m0 * 128];
        #pragma unroll 4
        for (int i = tid; i < 4096; i += 256) {
            int row = i >> 5, c = i & 31;
            *(uint4*)(smem + lev * AS_LEV + row * 528 + c * 16) = src[(size_t)row * 32 + c];
        }
    }

    // lane-dependent ldmatrix offsets
    const int g = lane >> 2;
    const int a_kadd = (lane >> 4) * 8;                // k elems
    const int b_kadd = ((lane >> 3) & 1) * 8;          // k elems
    uint32_t aRow[4], bRow[4];
    #pragma unroll
    for (int im = 0; im < 4; im++)
        aRow[im] = (uint32_t)((wm * 64 + im * 16 + (lane & 7) + ((lane >> 3) & 1) * 8) * 528);
    #pragma unroll
    for (int j2 = 0; j2 < 4; j2++)
        bRow[j2] = (uint32_t)((wn * 64 + j2 * 16 + (lane & 7) + ((lane >> 4) & 1) * 8) * 144);

    float acc[4][8][4];
    #pragma unroll
    for (int im = 0; im < 4; im++)
        #pragma unroll
        for (int jn = 0; jn < 8; jn++)
            #pragma unroll
            for (int c = 0; c < 4; c++) acc[im][jn][c] = 0.0f;

    float bestv[8];
    int   bestk[8];
    #pragma unroll
    for (int r = 0; r < 8; r++) { bestv[r] = 3.4e38f; bestk[r] = 0; }

    __syncthreads();

    // chunk i -> cb = i>>3 (256-code block), kc = i&7 (32-k slab).
    // B chunk row n (0..255): [64B lev0 k32][64B lev1 k32][16B pad]
    auto issue = [&](int i) {
        int cb = i >> 3, kc = i & 7;
        uint32_t dstbase = sbase + BS_OFF + (uint32_t)(i & 1) * BS_BUF;
        #pragma unroll
        for (int j = 0; j < 8; j++) {
            int f = j * 256 + tid;         // 0..2047
            int n = f >> 3, seg = f & 7;
            int lev = seg >> 2, kq = seg & 3;
            const char* src = (const char*)&g_b[lev][((size_t)(cb * 256 + n)) * Dd + kc * 32]
                            + kq * 16;
            cp16(dstbase + (uint32_t)n * 144 + seg * 16, src);
        }
        CP_COMMIT();
    };

    issue(0);

    for (int i = 0; i < NCHUNK; i++) {
        if (i + 1 < NCHUNK) {
            issue(i + 1);
            asm volatile("cp.async.wait_group 1;" ::: "memory");
        } else {
            asm volatile("cp.async.wait_group 0;" ::: "memory");
        }
        __syncthreads();

        const int cb = i >> 3, kc = i & 7;
        const uint32_t Bbase = sbase + BS_OFF + (uint32_t)(i & 1) * BS_BUF;

        #pragma unroll
        for (int s = 0; s < 2; s++) {      // two k16 slabs in the k32 chunk
            const int kglob = kc * 32 + s * 16;
            unsigned af0[4][4], af1[4][4], bf0[8][2], bf1[8][2];
            #pragma unroll
            for (int im = 0; im < 4; im++) {
                ldsm4(sbase + aRow[im] + (uint32_t)(kglob + a_kadd) * 2,
                      af0[im][0], af0[im][1], af0[im][2], af0[im][3]);
                ldsm4(sbase + AS_LEV + aRow[im] + (uint32_t)(kglob + a_kadd) * 2,
                      af1[im][0], af1[im][1], af1[im][2], af1[im][3]);
            }
            #pragma unroll
            for (int j2 = 0; j2 < 4; j2++) {
                unsigned r0, r1, r2, r3;
                ldsm4(Bbase + bRow[j2] + (uint32_t)(s * 32 + b_kadd * 2), r0, r1, r2, r3);
                bf0[j2 * 2][0] = r0;     bf0[j2 * 2][1] = r1;
                bf0[j2 * 2 + 1][0] = r2; bf0[j2 * 2 + 1][1] = r3;
                ldsm4(Bbase + bRow[j2] + (uint32_t)(64 + s * 32 + b_kadd * 2), r0, r1, r2, r3);
                bf1[j2 * 2][0] = r0;     bf1[j2 * 2][1] = r1;
                bf1[j2 * 2 + 1][0] = r2; bf1[j2 * 2 + 1][1] = r3;
            }
            #pragma unroll
            for (int im = 0; im < 4; im++)
                #pragma unroll
                for (int jn = 0; jn < 8; jn++) {
                    mma16816(acc[im][jn], af0[im], bf0[jn]);
                    mma16816(acc[im][jn], af1[im], bf0[jn]);
                    mma16816(acc[im][jn], af0[im], bf1[jn]);
                }
        }
        __syncthreads();   // protect buffer reuse by issue(i+2)

        if (kc == 7) {
            // epilogue for code block cb: bit-faithful score + per-row argmin
            const float* t2s = (const float*)(smem + T2_OFF);
            const float* t1s = (const float*)(smem + T1_OFF);
            #pragma unroll
            for (int im = 0; im < 4; im++) {
                float t1a = t1s[wm * 64 + im * 16 + g];
                float t1b = t1s[wm * 64 + im * 16 + g + 8];
                #pragma unroll
                for (int jn = 0; jn < 8; jn++) {
                    int kbase = cb * 256 + wn * 64 + jn * 8 + (lane & 3) * 2;
                    float t2a = t2s[kbase], t2b = t2s[kbase + 1];
                    float d0v = __fadd_rn(__fadd_rn(t1a, t2a), -2.0f * acc[im][jn][0]);
                    float d1v = __fadd_rn(__fadd_rn(t1a, t2b), -2.0f * acc[im][jn][1]);
                    if (d0v < bestv[im * 2]) { bestv[im * 2] = d0v; bestk[im * 2] = kbase; }
                    if (d1v < bestv[im * 2]) { bestv[im * 2] = d1v; bestk[im * 2] = kbase + 1; }
                    float d2v = __fadd_rn(__fadd_rn(t1b, t2a), -2.0f * acc[im][jn][2]);
                    float d3v = __fadd_rn(__fadd_rn(t1b, t2b), -2.0f * acc[im][jn][3]);
                    if (d2v < bestv[im * 2 + 1]) { bestv[im * 2 + 1] = d2v; bestk[im * 2 + 1] = kbase; }
                    if (d3v < bestv[im * 2 + 1]) { bestv[im * 2 + 1] = d3v; bestk[im * 2 + 1] = kbase + 1; }
                    #pragma unroll
                    for (int c = 0; c < 4; c++) acc[im][jn][c] = 0.0f;
                }
            }
        }
    }

    // quad reduction (lanes in same group of 4 hold same rows, different cols)
    #pragma unroll
    for (int off = 1; off <= 2; off <<= 1) {
        #pragma unroll
        for (int r = 0; r < 8; r++) {
            float ov = __shfl_xor_sync(0xffffffffu, bestv[r], off);
            int   ok = __shfl_xor_sync(0xffffffffu, bestk[r], off);
            if (ov < bestv[r] || (ov == bestv[r] && ok < bestk[r])) {
                bestv[r] = ov; bestk[r] = ok;
            }
        }
    }
    float* redv = (float*)(smem + REDV_OFF);
    int*   redk = (int*)(smem + REDK_OFF);
    if ((lane & 3) == 0) {
        #pragma unroll
        for (int im = 0; im < 4; im++) {
            #pragma unroll
            for (int hh = 0; hh < 2; hh++) {
                int row = wm * 64 + im * 16 + g + hh * 8;
                redv[row * 4 + wn] = bestv[im * 2 + hh];
                redk[row * 4 + wn] = bestk[im * 2 + hh];
            }
        }
    }
    __syncthreads();
    if (tid < 128) {
        float bv = redv[tid * 4];
        int   bk = redk[tid * 4];
        #pragma unroll
        for (int w = 1; w < 4; w++) {
            float v = redv[tid * 4 + w];
            int   k = redk[tid * 4 + w];
            if (v < bv || (v == bv && k < bk)) { bv = v; bk = k; }
        }
        g_idx[m0 + tid] = bk;
    }
}

// ---------------------------------------------------------------------------
// Gather z_q = emb[idx], write NCHW output, loss partials, indices as float.
__global__ void out_kernel(const float* __restrict__ z, const float* __restrict__ emb,
                           float* __restrict__ out, float* __restrict__ idx_out,
                           int has_idx) {
    __shared__ int   sidx[32];
    __shared__ float red[256];
    const int tid = threadIdx.x;
    const int p0  = blockIdx.x * 32;
    const int b   = p0 >> 12;
    const int hw0 = p0 & 4095;

    if (tid < 32) {
        int iv = g_idx[p0 + tid];
        sidx[tid] = iv;
        if (has_idx) idx_out[p0 + tid] = (float)iv;
    }
    __syncthreads();

    const int p  = tid & 31;
    const int dl = tid >> 5;
    const float* zb   = z   + (size_t)b * (size_t)(Dd * HW) + hw0 + p;
    float*       ob   = out + (size_t)b * (size_t)(Dd * HW) + hw0 + p;
    const float* erow = emb + (size_t)sidx[p] * Dd;

    float acc = 0.0f;
    #pragma unroll
    for (int db = 0; db < 32; db++) {
        int d = db * 8 + dl;
        float e  = erow[d];
        float zv = zb[(size_t)d * HW];
        ob[(size_t)d * HW] = e;
        float df = e - zv;
        acc = fmaf(df, df, acc);
    }

    red[tid] = acc;
    __syncthreads();
    for (int s = 128; s > 0; s >>= 1) {
        if (tid < s) red[tid] += red[tid + s];
        __syncthreads();
    }
    if (tid == 0) g_part[blockIdx.x] = red[0];
}

__global__ void loss_kernel(float* __restrict__ out_loss) {
    __shared__ double red[256];
    const int tid = threadIdx.x;
    double s = 0.0;
    #pragma unroll
    for (int i = 0; i < 8; i++) s += (double)g_part[tid * 8 + i];
    red[tid] = s;
    __syncthreads();
    for (int st = 128; st > 0; st >>= 1) {
        if (tid < st) red[tid] += red[tid + st];
        __syncthreads();
    }
    if (tid == 0) *out_loss = (float)(0.25 * (red[0] / (double)NOUT));
}

// ---------------------------------------------------------------------------
extern "C" void kernel_launch(void* const* d_in, const int* in_sizes, int n_in,
                              void* d_out, int out_size) {
    const float* z   = (const float*)d_in[0];
    const float* emb = (const float*)d_in[1];
    float* out = (float*)d_out;

    const int has_idx  = (out_size >= NOUT + NPIX) ? 1 : 0;
    const int has_loss = (out_size >= NOUT + NPIX + 1) ? 1 : 0;

    static int attr_done = 0;
    if (!attr_done) {
        cudaFuncSetAttribute(argmin_mma_kernel,
                             cudaFuncAttributeMaxDynamicSharedMemorySize, SM_TOTAL);
        attr_done = 1;
    }

    prep_b_kernel<<<KK * Dd / 256, 256>>>(emb);
    prep_a_kernel<<<512, 256>>>(z);
    t2_kernel<<<KK / 256, 256>>>(emb);
    argmin_mma_kernel<<<512, 256, SM_TOTAL>>>();
    out_kernel<<<NPIX / 32, 256>>>(z, emb, out, out + NOUT, has_idx);
    if (has_loss) loss_kernel<<<1, 256>>>(out + NOUT + NPIX);
}